// round 2
// baseline (speedup 1.0000x reference)
#include <cuda_runtime.h>
#include <cuda_bf16.h>
#include <cstddef>

// Problem constants (from reference setup_inputs)
#define HH   8      // heads
#define TQ   2048   // queries per head
#define TT   4096   // keys per head
#define DK   64     // head dim
#define BSZ  64     // block size
#define NB   64     // num key blocks per head (TT/BSZ)
#define NQG  (HH*TQ)        // 16384 total queries
#define PSTRIDE 68          // floats per partial record (64 acc + m + l + pad)

// Scratch for flash-style partials: [slot(2)][query(16384)][68]
__device__ float g_partial[2 * NQG * PSTRIDE];

// ---------------------------------------------------------------------------
// Kernel 1: one CTA per (head, block). Stage the K/V block in SMEM, scan this
// head's top2 index list for queries selecting this block, and for each match
// compute an unnormalized softmax partial (m, sum_exp, exp-weighted V acc).
// ---------------------------------------------------------------------------
__global__ __launch_bounds__(256, 4)
void partial_kernel(const float* __restrict__ q,
                    const float* __restrict__ k,
                    const float* __restrict__ v,
                    const int*   __restrict__ idx)
{
    __shared__ float ks[64 * PSTRIDE];      // K block, stride 68 (conflict-free)
    __shared__ float vs[64 * PSTRIDE];      // V block
    __shared__ float qsh[8][DK];            // per-warp q broadcast buffer
    __shared__ unsigned short qlist[TQ];    // matched queries (qq | mask<<12)
    __shared__ int nmatch;

    const int hh  = blockIdx.x >> 6;   // head
    const int bl  = blockIdx.x & 63;   // key block
    const int tid = threadIdx.x;

    if (tid == 0) nmatch = 0;

    // Stage K and V block rows (64 x 64 f32) into padded SMEM, float4 granular.
    const float4* kg  = (const float4*)(k + ((size_t)hh * TT + (size_t)bl * BSZ) * DK);
    const float4* vg  = (const float4*)(v + ((size_t)hh * TT + (size_t)bl * BSZ) * DK);
    float4* ks4 = (float4*)ks;
    float4* vs4 = (float4*)vs;
    #pragma unroll 4
    for (int i = tid; i < 64 * 16; i += 256) {
        int row = i >> 4, c = i & 15;
        ks4[row * 17 + c] = kg[row * 16 + c];
        vs4[row * 17 + c] = vg[row * 16 + c];
    }
    __syncthreads();   // nmatch visible, K/V staged

    // Scan this head's top2 indices for matches against block `bl`.
    const int2* idxh = (const int2*)(idx + (size_t)hh * TQ * 2);
    for (int qq = tid; qq < TQ; qq += 256) {
        int2 t2 = idxh[qq];
        int mask = (t2.x == bl ? 1 : 0) | (t2.y == bl ? 2 : 0);
        if (mask) {
            int pos = atomicAdd(&nmatch, 1);
            qlist[pos] = (unsigned short)(qq | (mask << 12));
        }
    }
    __syncthreads();
    const int n    = nmatch;
    const int warp = tid >> 5;
    const int lane = tid & 31;

    for (int e = warp; e < n; e += 8) {
        const unsigned short ent = qlist[e];
        const int qq   = ent & 0x0FFF;
        const int mask = ent >> 12;
        const int qg   = hh * TQ + qq;

        __syncwarp();  // previous iteration's qsh reads done
        // Broadcast q row into this warp's SMEM stripe
        float2 myq = ((const float2*)(q + (size_t)qg * DK))[lane];
        qsh[warp][2 * lane]     = myq.x;
        qsh[warp][2 * lane + 1] = myq.y;
        __syncwarp();

        // --- QK: lane handles keys {lane, lane+32} ---
        const float4* qs4 = (const float4*)qsh[warp];
        float s0 = 0.f, s1 = 0.f;
        const int k0 = lane, k1 = lane + 32;
        #pragma unroll
        for (int i = 0; i < 16; i++) {
            float4 qv = qs4[i];                 // broadcast, conflict-free
            float4 a  = ks4[k0 * 17 + i];
            float4 b  = ks4[k1 * 17 + i];
            s0 += qv.x * a.x + qv.y * a.y + qv.z * a.z + qv.w * a.w;
            s1 += qv.x * b.x + qv.y * b.y + qv.z * b.z + qv.w * b.w;
        }
        s0 *= 0.125f;  s1 *= 0.125f;            // 1/sqrt(64)

        // --- softmax partial over these 64 keys ---
        float m = fmaxf(s0, s1);
        #pragma unroll
        for (int o = 16; o > 0; o >>= 1) m = fmaxf(m, __shfl_xor_sync(0xFFFFFFFFu, m, o));
        float e0 = __expf(s0 - m), e1 = __expf(s1 - m);
        float ls = e0 + e1;
        #pragma unroll
        for (int o = 16; o > 0; o >>= 1) ls += __shfl_xor_sync(0xFFFFFFFFu, ls, o);

        // --- PV: lane owns dims {2*lane, 2*lane+1}; broadcast p via shfl ---
        float2 acc = make_float2(0.f, 0.f);
        #pragma unroll
        for (int j = 0; j < 32; j++) {
            float p   = __shfl_sync(0xFFFFFFFFu, e0, j);
            float2 vv = ((const float2*)(vs + j * PSTRIDE))[lane];
            acc.x += p * vv.x;  acc.y += p * vv.y;
        }
        #pragma unroll
        for (int j = 0; j < 32; j++) {
            float p   = __shfl_sync(0xFFFFFFFFu, e1, j);
            float2 vv = ((const float2*)(vs + (j + 32) * PSTRIDE))[lane];
            acc.x += p * vv.x;  acc.y += p * vv.y;
        }

        // --- write partial(s) (unnormalized) ---
        #pragma unroll
        for (int slot = 0; slot < 2; slot++) {
            if (mask & (1 << slot)) {
                float* dst = g_partial + ((size_t)slot * NQG + qg) * PSTRIDE;
                ((float2*)dst)[lane] = acc;
                if (lane == 0) { dst[64] = m; dst[65] = ls; }
            }
        }
    }
}

// ---------------------------------------------------------------------------
// Kernel 2: merge the two partials per query (flash-attention combine).
// 4 queries per 256-thread CTA; thread t handles one output dim.
// ---------------------------------------------------------------------------
__global__ __launch_bounds__(256)
void combine_kernel(float* __restrict__ out)
{
    const int t  = threadIdx.x & 63;
    const int qg = blockIdx.x * 4 + (threadIdx.x >> 6);
    const float* p0 = g_partial + (size_t)qg * PSTRIDE;
    const float* p1 = g_partial + ((size_t)NQG + qg) * PSTRIDE;
    const float m0 = p0[64], l0 = p0[65];
    const float m1 = p1[64], l1 = p1[65];
    const float M  = fmaxf(m0, m1);
    const float w0 = __expf(m0 - M), w1 = __expf(m1 - M);
    const float inv = 1.0f / (l0 * w0 + l1 * w1);
    out[(size_t)qg * DK + t] = (p0[t] * w0 + p1[t] * w1) * inv;
}

// ---------------------------------------------------------------------------
extern "C" void kernel_launch(void* const* d_in, const int* in_sizes, int n_in,
                              void* d_out, int out_size)
{
    const float* q = nullptr; const float* k = nullptr; const float* v = nullptr;
    const int* idx = nullptr;
    for (int i = 0; i < n_in; i++) {
        const int s = in_sizes[i];
        if (s == HH * TQ * DK && !q)         q = (const float*)d_in[i];        // 1,048,576
        else if (s == HH * TT * DK) {                                          // 2,097,152
            if (!k) k = (const float*)d_in[i];
            else if (!v) v = (const float*)d_in[i];
        }
        else if (s == HH * TQ * 2)           idx = (const int*)d_in[i];        // 32,768
        // s == 1 is the BS scalar (compile-time 64 here); ignored.
    }

    partial_kernel<<<HH * NB, 256>>>(q, k, v, idx);
    combine_kernel<<<NQG / 4, 256>>>((float*)d_out);
}

// round 3
// speedup vs baseline: 1.9084x; 1.9084x over previous
#include <cuda_runtime.h>
#include <cstddef>

#define HH   8
#define TQ   2048
#define TT   4096
#define DK   64
#define NB   64
#define NQG    (HH*TQ)     // 16384
#define NUNITS (HH*NB)     // 512
#define GRID_P 296         // 2 CTAs/SM on 148 SMs; ticket absorbs remainder

typedef unsigned long long ull;

// Scratch: flash partials. acc[2][NQG][64], ml4[q] = (m0,l0,m1,l1)
__device__ float  g_acc[2u * NQG * DK];
__device__ float4 g_ml4[NQG];
__device__ int    g_ticket = GRID_P;   // work-stealing cursor; combine resets

#define FMA2(d,a,b,c) asm("fma.rn.f32x2 %0, %1, %2, %3;" : "=l"(d) : "l"(a), "l"(b), "l"(c))

// ---- dynamic SMEM layout (float offsets) ----
// ks: 64 rows x 68 floats (pad -> conflict-free LDS.128 by key row)
// vs: same
// ubuf: per-warp 1024 floats; phase1 = q rows [8][64], phase2 = dup'd P [8][64] x float2
// qlist: 2048 ushort ; nmatch/next: ints
#define KS_OFF    0
#define VS_OFF    4352
#define UBUF_OFF  8704
#define QLIST_OFF 16896
#define NM_OFF    17920
#define SMEM_BYTES ((NM_OFF + 4) * 4)   // 71696

__global__ __launch_bounds__(256, 2)
void partial_kernel(const float* __restrict__ q,
                    const float* __restrict__ k,
                    const float* __restrict__ v,
                    const int*   __restrict__ idx)
{
    extern __shared__ float sm[];
    float* ks = sm + KS_OFF;
    float* vs = sm + VS_OFF;
    unsigned short* qlist = (unsigned short*)(sm + QLIST_OFF);
    int* nmatch = (int*)(sm + NM_OFF);
    int* nextu  = nmatch + 1;

    const int tid  = threadIdx.x;
    const int warp = tid >> 5;
    const int lane = tid & 31;
    float* ubuf = sm + UBUF_OFF + warp * 1024;

    int u = blockIdx.x;
    while (u < NUNITS) {
        const int hh = u >> 6, bl = u & 63;
        if (tid == 0) *nmatch = 0;

        // ---- stage K/V block (64x64 f32) into padded SMEM ----
        const float4* kg = (const float4*)(k + ((size_t)hh * TT + (size_t)bl * 64) * DK);
        const float4* vg = (const float4*)(v + ((size_t)hh * TT + (size_t)bl * 64) * DK);
        float4* ks4 = (float4*)ks;
        float4* vs4 = (float4*)vs;
        #pragma unroll
        for (int i = tid; i < 1024; i += 256) {
            int row = i >> 4, c = i & 15;
            ks4[row * 17 + c] = kg[i];
            vs4[row * 17 + c] = vg[i];
        }
        __syncthreads();

        // ---- scan this head's top2 list for matches ----
        const int2* idxh = (const int2*)(idx + (size_t)hh * TQ * 2);
        for (int qq = tid; qq < TQ; qq += 256) {
            int2 t2 = idxh[qq];
            int mk = (t2.x == bl ? 1 : 0) | (t2.y == bl ? 2 : 0);
            if (mk) {
                int pos = atomicAdd(nmatch, 1);
                qlist[pos] = (unsigned short)(qq | (mk << 12));
            }
        }
        __syncthreads();
        const int n = *nmatch;

        // ---- warp-tiles of 8 queries ----
        for (int base = warp * 8; base < n; base += 64) {
            const int nt = min(8, n - base);
            int qgr[8], mkr[8];
            #pragma unroll
            for (int r = 0; r < 8; r++) {
                int e = base + ((r < nt) ? r : 0);
                unsigned short ent = qlist[e];
                qgr[r] = hh * TQ + (ent & 0x0FFF);
                mkr[r] = (r < nt) ? (ent >> 12) : 0;
            }

            __syncwarp();   // prior tile's ubuf reads done
            #pragma unroll
            for (int r = 0; r < 8; r++) {
                float2 qv = ((const float2*)(q + (size_t)qgr[r] * DK))[lane];
                ((float2*)(ubuf + r * 64))[lane] = qv;
            }
            __syncwarp();

            // ---- QK: lane owns keys {lane, lane+32}; f32x2 pairs along dk ----
            ull sA[8], sB[8];
            #pragma unroll
            for (int r = 0; r < 8; r++) { sA[r] = 0ull; sB[r] = 0ull; }
            {
                const ulonglong2* ka4 = (const ulonglong2*)(ks + lane * 68);
                const ulonglong2* kb4 = (const ulonglong2*)(ks + (lane + 32) * 68);
                #pragma unroll
                for (int i = 0; i < 16; i++) {
                    ulonglong2 ka = ka4[i];
                    ulonglong2 kb = kb4[i];
                    #pragma unroll
                    for (int r = 0; r < 8; r++) {
                        ulonglong2 qv = ((const ulonglong2*)(ubuf + r * 64))[i];
                        FMA2(sA[r], qv.x, ka.x, sA[r]);
                        FMA2(sA[r], qv.y, ka.y, sA[r]);
                        FMA2(sB[r], qv.x, kb.x, sB[r]);
                        FMA2(sB[r], qv.y, kb.y, sB[r]);
                    }
                }
            }
            __syncwarp();   // q reads done before P overwrites ubuf

            // ---- softmax partial; store P duplicated (p,p) for FMA2 PV ----
            float mv[8], lv[8];
            #pragma unroll
            for (int r = 0; r < 8; r++) {
                unsigned lo, hi;
                asm("mov.b64 {%0,%1}, %2;" : "=r"(lo), "=r"(hi) : "l"(sA[r]));
                float s0 = (__uint_as_float(lo) + __uint_as_float(hi)) * 0.125f;
                asm("mov.b64 {%0,%1}, %2;" : "=r"(lo), "=r"(hi) : "l"(sB[r]));
                float s1 = (__uint_as_float(lo) + __uint_as_float(hi)) * 0.125f;
                float m = fmaxf(s0, s1);
                #pragma unroll
                for (int o = 16; o; o >>= 1) m = fmaxf(m, __shfl_xor_sync(0xFFFFFFFFu, m, o));
                float e0 = __expf(s0 - m), e1 = __expf(s1 - m);
                float l = e0 + e1;
                #pragma unroll
                for (int o = 16; o; o >>= 1) l += __shfl_xor_sync(0xFFFFFFFFu, l, o);
                ull d0, d1;
                unsigned e0u = __float_as_uint(e0), e1u = __float_as_uint(e1);
                asm("mov.b64 %0, {%1,%1};" : "=l"(d0) : "r"(e0u));
                asm("mov.b64 %0, {%1,%1};" : "=l"(d1) : "r"(e1u));
                ((ull*)ubuf)[r * 64 + lane]      = d0;   // key = lane
                ((ull*)ubuf)[r * 64 + lane + 32] = d1;   // key = lane+32
                mv[r] = m; lv[r] = l;
            }
            __syncwarp();

            // ---- PV: lane owns dims {2*lane, 2*lane+1} as one f32x2 acc ----
            ull acc[8];
            #pragma unroll
            for (int r = 0; r < 8; r++) acc[r] = 0ull;
            {
                const ull* vr = (const ull*)vs;     // row j at 34*j, lane's pair at +lane
                const ull* pb = (const ull*)ubuf;   // dup'd (p,p) pairs, broadcast reads
                #pragma unroll 8
                for (int j = 0; j < 64; j++) {
                    ull v2 = vr[j * 34 + lane];
                    #pragma unroll
                    for (int r = 0; r < 8; r++) {
                        FMA2(acc[r], pb[r * 64 + j], v2, acc[r]);
                    }
                }
            }

            // ---- write partials (unnormalized acc + m,l) ----
            #pragma unroll
            for (int r = 0; r < 8; r++) {
                if (mkr[r] & 1) {
                    ((ull*)(g_acc + (size_t)qgr[r] * DK))[lane] = acc[r];
                    if (lane == 0)
                        *((float2*)&g_ml4[qgr[r]].x) = make_float2(mv[r], lv[r]);
                }
                if (mkr[r] & 2) {
                    ((ull*)(g_acc + ((size_t)NQG + qgr[r]) * DK))[lane] = acc[r];
                    if (lane == 0)
                        *((float2*)&g_ml4[qgr[r]].z) = make_float2(mv[r], lv[r]);
                }
            }
        }

        // ---- steal next unit ----
        if (tid == 0) *nextu = atomicAdd(&g_ticket, 1);
        __syncthreads();    // also protects ks/vs/qlist restage
        u = *nextu;
    }
}

// ---------------------------------------------------------------------------
// Combine: 16 threads per query, float4 per thread. Resets ticket for next
// replay (combine runs strictly after partial on the same stream).
// ---------------------------------------------------------------------------
__global__ __launch_bounds__(256)
void combine_kernel(float* __restrict__ out)
{
    if (blockIdx.x == 0 && threadIdx.x == 0) g_ticket = GRID_P;
    const int t  = blockIdx.x * 256 + threadIdx.x;
    const int qg = t >> 4;
    const int c  = t & 15;
    const float4 ml = g_ml4[qg];
    const float4 a = ((const float4*)(g_acc + (size_t)qg * DK))[c];
    const float4 b = ((const float4*)(g_acc + ((size_t)NQG + qg) * DK))[c];
    const float M  = fmaxf(ml.x, ml.z);
    float w0 = __expf(ml.x - M);
    float w1 = __expf(ml.z - M);
    const float inv = 1.0f / (ml.y * w0 + ml.w * w1);
    w0 *= inv; w1 *= inv;
    float4 o;
    o.x = a.x * w0 + b.x * w1;
    o.y = a.y * w0 + b.y * w1;
    o.z = a.z * w0 + b.z * w1;
    o.w = a.w * w0 + b.w * w1;
    ((float4*)out)[t] = o;
}

// ---------------------------------------------------------------------------
extern "C" void kernel_launch(void* const* d_in, const int* in_sizes, int n_in,
                              void* d_out, int out_size)
{
    const float* q = nullptr; const float* k = nullptr; const float* v = nullptr;
    const int* idx = nullptr;
    for (int i = 0; i < n_in; i++) {
        const int s = in_sizes[i];
        if (s == HH * TQ * DK && !q)  q = (const float*)d_in[i];       // 1,048,576
        else if (s == HH * TT * DK) {                                   // 2,097,152
            if (!k) k = (const float*)d_in[i];
            else if (!v) v = (const float*)d_in[i];
        }
        else if (s == HH * TQ * 2)    idx = (const int*)d_in[i];        // 32,768
    }

    cudaFuncSetAttribute(partial_kernel,
                         cudaFuncAttributeMaxDynamicSharedMemorySize, SMEM_BYTES);
    partial_kernel<<<GRID_P, 256, SMEM_BYTES>>>(q, k, v, idx);
    combine_kernel<<<(NQG * 16) / 256, 256>>>((float*)d_out);
}